// round 7
// baseline (speedup 1.0000x reference)
#include <cuda_runtime.h>
#include <math.h>

#define BATCH 256
#define SEQ   512
#define ISZ   256
#define HSZ   512
#define G4    2048   // 4*HSZ gate-interleaved: col j = u*4 + g, g in {i,f,g,o}

typedef unsigned long long ull;

// ---------------- device scratch (allocation-free) ----------------
__device__ float g_xu[(size_t)SEQ * BATCH * G4];  // xu[t][b][j]
__device__ float g_h[2][BATCH * HSZ];             // double-buffered hidden state
__device__ unsigned g_arrive;                     // grid-sync counter (reset by xu)

// ---------------- f32x2 helpers ----------------
__device__ __forceinline__ ull fma2(ull a, ull b, ull c) {
    ull d;
    asm("fma.rn.f32x2 %0, %1, %2, %3;" : "=l"(d) : "l"(a), "l"(b), "l"(c));
    return d;
}
__device__ __forceinline__ ull dup2(float x) {
    ull d;
    asm("mov.b64 %0, {%1, %1};" : "=l"(d) : "f"(x));
    return d;
}
__device__ __forceinline__ float2 unpk(ull v) {
    float2 r;
    asm("mov.b64 {%0, %1}, %2;" : "=f"(r.x), "=f"(r.y) : "l"(v));
    return r;
}
__device__ __forceinline__ float fsig(float x)  { return 1.0f / (1.0f + __expf(-x)); }
__device__ __forceinline__ float ftanh(float x) { return 2.0f / (1.0f + __expf(-2.0f * x)) - 1.0f; }

__device__ __forceinline__ void arrive_release(unsigned* p) {
    asm volatile("red.release.gpu.global.add.u32 [%0], 1;" :: "l"(p) : "memory");
}
__device__ __forceinline__ unsigned poll_acquire(const unsigned* p) {
    unsigned v;
    asm volatile("ld.acquire.gpu.global.u32 %0, [%1];" : "=r"(v) : "l"(p) : "memory");
    return v;
}

// ============ phase 1: xu = x @ Wu (interleaved on the fly) + bias ==========
#define XBM 64
#define XBN 64
#define XBK 16
#define XAS 34

__global__ __launch_bounds__(256) void xu_kernel(
    const float* __restrict__ x,
    const float* __restrict__ Wui, const float* __restrict__ Wuf,
    const float* __restrict__ Wug, const float* __restrict__ Wuo,
    const float* __restrict__ bi,  const float* __restrict__ bf,
    const float* __restrict__ bg,  const float* __restrict__ bo) {
    __shared__ float As[XBM * XAS];
    __shared__ float Bs[XBK * XBN];

    if (blockIdx.x == 0 && blockIdx.y == 0 && threadIdx.x == 0) g_arrive = 0u;

    int m0 = blockIdx.y * XBM;
    int n0 = blockIdx.x * XBN;
    int tid = threadIdx.x;
    int tx = tid & 15;
    int ty = tid >> 4;

    int prow = tid >> 2;
    int pkof = (tid & 3) * 4;
    int brow = tid >> 4;
    int bu   = tid & 15;

    int m = m0 + prow;
    int t = m >> 8;
    int b = m & 255;
    const float* aptr = x + (size_t)b * (SEQ * ISZ) + (size_t)t * ISZ + pkof;
    int ubase = (n0 >> 2) + bu;

    ull acc[4][2] = {};

    for (int k0 = 0; k0 < ISZ; k0 += XBK) {
        float4 av = *(const float4*)(aptr + k0);
        *(float2*)&As[prow * XAS + 2 * (pkof + 0)] = make_float2(av.x, av.x);
        *(float2*)&As[prow * XAS + 2 * (pkof + 1)] = make_float2(av.y, av.y);
        *(float2*)&As[prow * XAS + 2 * (pkof + 2)] = make_float2(av.z, av.z);
        *(float2*)&As[prow * XAS + 2 * (pkof + 3)] = make_float2(av.w, av.w);
        int kr = (k0 + brow) * HSZ + ubase;
        Bs[brow * XBN + bu * 4 + 0] = Wui[kr];
        Bs[brow * XBN + bu * 4 + 1] = Wuf[kr];
        Bs[brow * XBN + bu * 4 + 2] = Wug[kr];
        Bs[brow * XBN + bu * 4 + 3] = Wuo[kr];
        __syncthreads();

#pragma unroll
        for (int kk = 0; kk < XBK; kk++) {
            ulonglong2 b2 = *(const ulonglong2*)&Bs[kk * XBN + tx * 4];
#pragma unroll
            for (int r = 0; r < 4; r++) {
                ull a2 = *(const ull*)&As[(ty * 4 + r) * XAS + 2 * kk];
                acc[r][0] = fma2(a2, b2.x, acc[r][0]);
                acc[r][1] = fma2(a2, b2.y, acc[r][1]);
            }
        }
        __syncthreads();
    }

    int u = (n0 >> 2) + tx;
    float4 bias = {bi[u], bf[u], bg[u], bo[u]};
#pragma unroll
    for (int r = 0; r < 4; r++) {
        float2 lo = unpk(acc[r][0]);
        float2 hi = unpk(acc[r][1]);
        float4 ov = {lo.x + bias.x, lo.y + bias.y, hi.x + bias.z, hi.y + bias.w};
        *(float4*)(g_xu + (size_t)(m0 + ty * 4 + r) * G4 + n0 + tx * 4) = ov;
    }
}

// ============ phase 2: PERSISTENT, all 512 steps =============================
// 128 blocks (64 n-tiles x 2 b-tiles), tile = 128 batch x 32 gate-cols.
// 256 threads = 4 K-quarters x 64 threads; 8x8 microtile per thread (f32x2
// row-pair accumulators). W_h slice 512x32 in smem once; A staged per-group
// in 16-k ping-pong chunks (conflict-free STS); 4 partials combined via smem.
#define PBLKS 128
#define PM 128          // batch rows per block
#define PN 32           // gate cols per block
#define NG 4            // K-quarter groups
#define GK 128          // K per group
#define CH 16           // k per staged chunk
#define NCH 8           // chunks per group
#define EPS2 36         // EP row stride (32 + 4 pad)
#define WHS_F (HSZ * PN)        // 16384 floats (64KB)
#define ABUF_F (CH * PM)        // 2048 floats per buffer
#define EP_F (PM * EPS2)        // 4608 floats per group
#define P_SMEM_BYTES ((WHS_F + NG * 2 * ABUF_F + NG * EP_F) * 4)   // 204800 B

extern __shared__ float s_mem[];

__global__ __launch_bounds__(256, 1) void lstm_persistent(
    float* __restrict__ out,
    const float* __restrict__ Whi, const float* __restrict__ Whf,
    const float* __restrict__ Whg, const float* __restrict__ Who) {
    float* Whs  = s_mem;                       // [512][32]
    float* Abuf = s_mem + WHS_F;               // [4 groups][2 pp][16][128]
    float* EP   = s_mem + WHS_F + NG * 2 * ABUF_F;   // [4 groups][128][36]

    int tid = threadIdx.x;
    int n0 = (blockIdx.x & 63) * PN;
    int b0 = (blockIdx.x >> 6) * PM;
    int g  = tid >> 6;                 // K-quarter
    int gt = tid & 63;
    int tx = gt & 3;                   // col-oct (8 cols)
    int ty = gt >> 2;                  // row-oct (8 rows)
    int er = tid >> 1;                 // epilogue row 0..127
    int ec = (tid & 1) * 16;           // epilogue col base (4 units)

    // ---- stage W_h slice (gate-interleaved on the fly), once ----
    for (int idx = tid; idx < WHS_F; idx += 256) {
        int k = idx >> 5, c = idx & 31;
        int u = (n0 >> 2) + (c >> 2), gg = c & 3;
        const float* W = (gg == 0) ? Whi : (gg == 1) ? Whf : (gg == 2) ? Whg : Who;
        Whs[idx] = W[k * HSZ + u];
    }
    __syncthreads();

    float creg[4] = {0.f, 0.f, 0.f, 0.f};       // 4 units x 1 batch row
    float* A0 = Abuf + g * (2 * ABUF_F);
    float* A1 = A0 + ABUF_F;
    const float* WBg = Whs + g * (GK * PN) + tx * 8;
    float* EPg = EP + g * EP_F;
    int rowA = gt, rowB = gt + 64;
    int u0 = (n0 >> 2) + (ec >> 2);

    for (int t = 0; t < SEQ; t++) {
        const float* __restrict__ h_in = g_h[t & 1];
        float* __restrict__ h_out = (t == SEQ - 1) ? out : g_h[(t + 1) & 1];

        // prefetch this thread's 16 xu gate values (epilogue)
        const float* xp = g_xu + ((size_t)t * BATCH + b0 + er) * G4 + n0 + ec;
        float4 xv0 = __ldcg((const float4*)xp);
        float4 xv1 = __ldcg((const float4*)(xp + 4));
        float4 xv2 = __ldcg((const float4*)(xp + 8));
        float4 xv3 = __ldcg((const float4*)(xp + 12));

        ull acc[4][8];
#pragma unroll
        for (int i = 0; i < 4; i++)
#pragma unroll
            for (int j = 0; j < 8; j++) acc[i][j] = 0ull;

        if (t > 0) {
            const float* apA = h_in + (size_t)(b0 + rowA) * HSZ + g * GK;
            const float* apB = h_in + (size_t)(b0 + rowB) * HSZ + g * GK;
            float4 p[8];
            p[0] = __ldcg((const float4*)(apA + 0));
            p[1] = __ldcg((const float4*)(apA + 4));
            p[2] = __ldcg((const float4*)(apA + 8));
            p[3] = __ldcg((const float4*)(apA + 12));
            p[4] = __ldcg((const float4*)(apB + 0));
            p[5] = __ldcg((const float4*)(apB + 4));
            p[6] = __ldcg((const float4*)(apB + 8));
            p[7] = __ldcg((const float4*)(apB + 12));

            // store chunk 0 -> A0 (transposed; bank = row = lane, conflict-free)
#pragma unroll
            for (int q = 0; q < 4; q++) {
                A0[(q * 4 + 0) * PM + rowA] = (&p[q].x)[0];
                A0[(q * 4 + 1) * PM + rowA] = (&p[q].x)[1];
                A0[(q * 4 + 2) * PM + rowA] = (&p[q].x)[2];
                A0[(q * 4 + 3) * PM + rowA] = (&p[q].x)[3];
                A0[(q * 4 + 0) * PM + rowB] = (&p[q + 4].x)[0];
                A0[(q * 4 + 1) * PM + rowB] = (&p[q + 4].x)[1];
                A0[(q * 4 + 2) * PM + rowB] = (&p[q + 4].x)[2];
                A0[(q * 4 + 3) * PM + rowB] = (&p[q + 4].x)[3];
            }
            __syncthreads();

            for (int s = 0; s < NCH; s++) {
                if (s < NCH - 1) {
                    int ko = (s + 1) * CH;
                    p[0] = __ldcg((const float4*)(apA + ko + 0));
                    p[1] = __ldcg((const float4*)(apA + ko + 4));
                    p[2] = __ldcg((const float4*)(apA + ko + 8));
                    p[3] = __ldcg((const float4*)(apA + ko + 12));
                    p[4] = __ldcg((const float4*)(apB + ko + 0));
                    p[5] = __ldcg((const float4*)(apB + ko + 4));
                    p[6] = __ldcg((const float4*)(apB + ko + 8));
                    p[7] = __ldcg((const float4*)(apB + ko + 12));
                }

                const float* Ac = (s & 1) ? A1 : A0;
                const float* WBs = WBg + (s * CH) * PN;
#pragma unroll
                for (int kk = 0; kk < CH; kk++) {
                    ulonglong2 aLo = *(const ulonglong2*)&Ac[kk * PM + ty * 8];
                    ulonglong2 aHi = *(const ulonglong2*)&Ac[kk * PM + ty * 8 + 4];
                    float4 bLo = *(const float4*)&WBs[kk * PN];
                    float4 bHi = *(const float4*)&WBs[kk * PN + 4];
                    ull bd0 = dup2(bLo.x), bd1 = dup2(bLo.y);
                    ull bd2 = dup2(bLo.z), bd3 = dup2(bLo.w);
                    ull bd4 = dup2(bHi.x), bd5 = dup2(bHi.y);
                    ull bd6 = dup2(bHi.z), bd7 = dup2(bHi.w);
                    ull a0 = aLo.x, a1 = aLo.y, a2 = aHi.x, a3 = aHi.y;
                    acc[0][0] = fma2(a0, bd0, acc[0][0]);
                    acc[1][0] = fma2(a1, bd0, acc[1][0]);
                    acc[2][0] = fma2(a2, bd0, acc[2][0]);
                    acc[3][0] = fma2(a3, bd0, acc[3][0]);
                    acc[0][1] = fma2(a0, bd1, acc[0][1]);
                    acc[1][1] = fma2(a1, bd1, acc[1][1]);
                    acc[2][1] = fma2(a2, bd1, acc[2][1]);
                    acc[3][1] = fma2(a3, bd1, acc[3][1]);
                    acc[0][2] = fma2(a0, bd2, acc[0][2]);
                    acc[1][2] = fma2(a1, bd2, acc[1][2]);
                    acc[2][2] = fma2(a2, bd2, acc[2][2]);
                    acc[3][2] = fma2(a3, bd2, acc[3][2]);
                    acc[0][3] = fma2(a0, bd3, acc[0][3]);
                    acc[1][3] = fma2(a1, bd3, acc[1][3]);
                    acc[2][3] = fma2(a2, bd3, acc[2][3]);
                    acc[3][3] = fma2(a3, bd3, acc[3][3]);
                    acc[0][4] = fma2(a0, bd4, acc[0][4]);
                    acc[1][4] = fma2(a1, bd4, acc[1][4]);
                    acc[2][4] = fma2(a2, bd4, acc[2][4]);
                    acc[3][4] = fma2(a3, bd4, acc[3][4]);
                    acc[0][5] = fma2(a0, bd5, acc[0][5]);
                    acc[1][5] = fma2(a1, bd5, acc[1][5]);
                    acc[2][5] = fma2(a2, bd5, acc[2][5]);
                    acc[3][5] = fma2(a3, bd5, acc[3][5]);
                    acc[0][6] = fma2(a0, bd6, acc[0][6]);
                    acc[1][6] = fma2(a1, bd6, acc[1][6]);
                    acc[2][6] = fma2(a2, bd6, acc[2][6]);
                    acc[3][6] = fma2(a3, bd6, acc[3][6]);
                    acc[0][7] = fma2(a0, bd7, acc[0][7]);
                    acc[1][7] = fma2(a1, bd7, acc[1][7]);
                    acc[2][7] = fma2(a2, bd7, acc[2][7]);
                    acc[3][7] = fma2(a3, bd7, acc[3][7]);
                }

                if (s < NCH - 1) {
                    float* An = (s & 1) ? A0 : A1;
#pragma unroll
                    for (int q = 0; q < 4; q++) {
                        An[(q * 4 + 0) * PM + rowA] = (&p[q].x)[0];
                        An[(q * 4 + 1) * PM + rowA] = (&p[q].x)[1];
                        An[(q * 4 + 2) * PM + rowA] = (&p[q].x)[2];
                        An[(q * 4 + 3) * PM + rowA] = (&p[q].x)[3];
                        An[(q * 4 + 0) * PM + rowB] = (&p[q + 4].x)[0];
                        An[(q * 4 + 1) * PM + rowB] = (&p[q + 4].x)[1];
                        An[(q * 4 + 2) * PM + rowB] = (&p[q + 4].x)[2];
                        An[(q * 4 + 3) * PM + rowB] = (&p[q + 4].x)[3];
                    }
                }
                __syncthreads();
            }
        }

        // ---- write this group's partial 8x8 tile to EP ----
#pragma unroll
        for (int rp = 0; rp < 4; rp++) {
            float2 v0 = unpk(acc[rp][0]);
            float2 v1 = unpk(acc[rp][1]);
            float2 v2 = unpk(acc[rp][2]);
            float2 v3 = unpk(acc[rp][3]);
            float2 v4 = unpk(acc[rp][4]);
            float2 v5 = unpk(acc[rp][5]);
            float2 v6 = unpk(acc[rp][6]);
            float2 v7 = unpk(acc[rp][7]);
            int r0 = ty * 8 + 2 * rp;
            float4 lo0 = {v0.x, v1.x, v2.x, v3.x};
            float4 lo1 = {v4.x, v5.x, v6.x, v7.x};
            float4 hi0 = {v0.y, v1.y, v2.y, v3.y};
            float4 hi1 = {v4.y, v5.y, v6.y, v7.y};
            *(float4*)&EPg[r0 * EPS2 + tx * 8]           = lo0;
            *(float4*)&EPg[r0 * EPS2 + tx * 8 + 4]       = lo1;
            *(float4*)&EPg[(r0 + 1) * EPS2 + tx * 8]     = hi0;
            *(float4*)&EPg[(r0 + 1) * EPS2 + tx * 8 + 4] = hi1;
        }
        __syncthreads();

        // ---- combine 4 partials + fused LSTM cell (1 row x 4 units) ----
        const float* e0 = EP + er * EPS2 + ec;
        const float* e1 = e0 + EP_F;
        const float* e2 = e1 + EP_F;
        const float* e3 = e2 + EP_F;
        float4 s0, s1, s2, s3;
#define SUM4(dst, off) { \
        float4 a_ = *(const float4*)(e0 + off); \
        float4 b_ = *(const float4*)(e1 + off); \
        float4 c_ = *(const float4*)(e2 + off); \
        float4 d_ = *(const float4*)(e3 + off); \
        dst.x = a_.x + b_.x + c_.x + d_.x; \
        dst.y = a_.y + b_.y + c_.y + d_.y; \
        dst.z = a_.z + b_.z + c_.z + d_.z; \
        dst.w = a_.w + b_.w + c_.w + d_.w; }
        SUM4(s0, 0); SUM4(s1, 4); SUM4(s2, 8); SUM4(s3, 12);
#undef SUM4

        float4 hv;
        {
            float it = fsig (s0.x + xv0.x);
            float ft = fsig (s0.y + xv0.y);
            float gt_ = ftanh(s0.z + xv0.z);
            float ot = fsig (s0.w + xv0.w);
            creg[0] = ft * creg[0] + it * gt_;
            hv.x = ot * ftanh(creg[0]);
        }
        {
            float it = fsig (s1.x + xv1.x);
            float ft = fsig (s1.y + xv1.y);
            float gt_ = ftanh(s1.z + xv1.z);
            float ot = fsig (s1.w + xv1.w);
            creg[1] = ft * creg[1] + it * gt_;
            hv.y = ot * ftanh(creg[1]);
        }
        {
            float it = fsig (s2.x + xv2.x);
            float ft = fsig (s2.y + xv2.y);
            float gt_ = ftanh(s2.z + xv2.z);
            float ot = fsig (s2.w + xv2.w);
            creg[2] = ft * creg[2] + it * gt_;
            hv.z = ot * ftanh(creg[2]);
        }
        {
            float it = fsig (s3.x + xv3.x);
            float ft = fsig (s3.y + xv3.y);
            float gt_ = ftanh(s3.z + xv3.z);
            float ot = fsig (s3.w + xv3.w);
            creg[3] = ft * creg[3] + it * gt_;
            hv.w = ot * ftanh(creg[3]);
        }
        *(float4*)&h_out[(size_t)(b0 + er) * HSZ + u0] = hv;

        // ---- grid-wide sync (wrap-safe compare; tight acquire spin) ----
        if (t < SEQ - 1) {
            __syncthreads();
            if (tid == 0) {
                arrive_release(&g_arrive);
                unsigned target = (unsigned)(t + 1) * (unsigned)PBLKS;
                while ((int)(poll_acquire(&g_arrive) - target) < 0) { }
            }
            __syncthreads();
        }
    }
}

// ---------------- launch ----------------------------------------------------
extern "C" void kernel_launch(void* const* d_in, const int* in_sizes, int n_in,
                              void* d_out, int out_size) {
    const float* x   = (const float*)d_in[0];
    const float* Wui = (const float*)d_in[1];
    const float* Whi = (const float*)d_in[2];
    const float* bi  = (const float*)d_in[3];
    const float* Wuf = (const float*)d_in[4];
    const float* Whf = (const float*)d_in[5];
    const float* bf  = (const float*)d_in[6];
    const float* Wug = (const float*)d_in[7];
    const float* Whg = (const float*)d_in[8];
    const float* bg  = (const float*)d_in[9];
    const float* Wuo = (const float*)d_in[10];
    const float* Who = (const float*)d_in[11];
    const float* bo  = (const float*)d_in[12];
    float* out = (float*)d_out;

    cudaFuncSetAttribute(lstm_persistent,
                         cudaFuncAttributeMaxDynamicSharedMemorySize, P_SMEM_BYTES);

    dim3 xu_grid(G4 / XBN, (SEQ * BATCH) / XBM);   // (32, 2048)
    xu_kernel<<<xu_grid, 256>>>(x, Wui, Wuf, Wug, Wuo, bi, bf, bg, bo);

    lstm_persistent<<<PBLKS, 256, P_SMEM_BYTES>>>(out, Whi, Whf, Whg, Who);
}